// round 15
// baseline (speedup 1.0000x reference)
#include <cuda_runtime.h>
#include <cuda_fp16.h>
#include <math.h>
#include <stdint.h>

// Problem constants
static constexpr int BATCH = 32;
static constexpr int SEQ   = 512;
static constexpr int DIM   = 768;
static constexpr int HEADS = 12;
static constexpr int HDIM  = 64;
static constexpr int MROWS = BATCH * SEQ;   // 16384
static constexpr int DFF   = 3072;

// Scratch (device globals — allocation-free rule)
__device__ __half h_ln  [MROWS * DIM];
__device__ __half h_q   [MROWS * DIM];
__device__ __half h_k   [MROWS * DIM];
__device__ __half h_v   [MROWS * DIM];
__device__ __half h_att [MROWS * DIM];
__device__ __half h_gelu[MROWS * DFF];
__device__ float  g_out1[MROWS * DIM];
__device__ __half h_w   [4 * DIM * DIM + 2 * DIM * DFF];
__device__ float  g_bqkv[3 * DIM];
__device__ unsigned long long g_mask[BATCH * SEQ * 8];

// ---------------------------------------------------------------------------
// Helpers
// ---------------------------------------------------------------------------
__device__ __forceinline__ uint32_t smem_u32(const void* p) {
    uint32_t a;
    asm("{ .reg .u64 t; cvta.to.shared.u64 t, %1; cvt.u32.u64 %0, t; }" : "=r"(a) : "l"(p));
    return a;
}
__device__ __forceinline__ uint32_t pack_h2(float a, float b) {
    __half2 t = __floats2half2_rn(a, b);
    return *reinterpret_cast<uint32_t*>(&t);
}
__device__ __forceinline__ uint32_t ex2_h2(uint32_t t) {
    uint32_t r;
    asm("ex2.approx.f16x2 %0, %1;" : "=r"(r) : "r"(t));
    return r;
}
__device__ __forceinline__ void mma_f16(float* c, uint32_t a0, uint32_t a1,
                                        uint32_t a2, uint32_t a3,
                                        uint32_t b0, uint32_t b1) {
    asm volatile(
        "mma.sync.aligned.m16n8k16.row.col.f32.f16.f16.f32 "
        "{%0,%1,%2,%3}, {%4,%5,%6,%7}, {%8,%9}, {%0,%1,%2,%3};"
        : "+f"(c[0]), "+f"(c[1]), "+f"(c[2]), "+f"(c[3])
        : "r"(a0), "r"(a1), "r"(a2), "r"(a3), "r"(b0), "r"(b1));
}
#define LDSM4(r0, r1, r2, r3, addr)                                            \
    asm volatile("ldmatrix.sync.aligned.m8n8.x4.shared.b16 {%0,%1,%2,%3}, [%4];" \
        : "=r"(r0), "=r"(r1), "=r"(r2), "=r"(r3) : "r"(addr))
#define LDSM4T(r0, r1, r2, r3, addr)                                           \
    asm volatile("ldmatrix.sync.aligned.m8n8.x4.trans.shared.b16 {%0,%1,%2,%3}, [%4];" \
        : "=r"(r0), "=r"(r1), "=r"(r2), "=r"(r3) : "r"(addr))
#define CP_ASYNC16(dst, src) \
    asm volatile("cp.async.cg.shared.global [%0], [%1], 16;" :: "r"(dst), "l"(src))
#define CP_COMMIT()  asm volatile("cp.async.commit_group;" ::: "memory")
#define CP_WAIT(N)   asm volatile("cp.async.wait_group %0;" :: "n"(N) : "memory")

// ---------------------------------------------------------------------------
// Prep A: weights fp32->fp16. Wq/Wk/Wv packed FUSED: h_w[k*2304 + c].
// ---------------------------------------------------------------------------
static constexpr int WELEM = DIM * DIM;               // 589824
static constexpr int FELEM = DIM * DFF;               // 2359296
static constexpr int TOTW  = 4 * WELEM + 2 * FELEM;
static constexpr int PREPW_BLOCKS = TOTW / (256 * 8) + 2;

__global__ __launch_bounds__(256) void prep_weights(
    const float* __restrict__ wq, const float* __restrict__ wk,
    const float* __restrict__ wv, const float* __restrict__ wo,
    const float* __restrict__ w1, const float* __restrict__ w2,
    const float* __restrict__ bq, const float* __restrict__ bk,
    const float* __restrict__ bv)
{
    size_t E = ((size_t)blockIdx.x * 256 + threadIdx.x) * 8;
    if (E < (size_t)TOTW) {
        const float* src; size_t off;
        if (E < 3 * (size_t)WELEM) {
            size_t k = E / 2304, c = E - k * 2304;
            int sel = (int)(c / DIM);
            src = (sel == 0) ? wq : (sel == 1) ? wk : wv;
            off = k * DIM + (c - (size_t)sel * DIM);
        } else if (E < 4 * (size_t)WELEM) { src = wo; off = E - 3 * (size_t)WELEM; }
        else if (E < 4 * (size_t)WELEM + FELEM) { src = w1; off = E - 4 * (size_t)WELEM; }
        else { src = w2; off = E - 4 * (size_t)WELEM - FELEM; }
        float4 v0 = *(const float4*)(src + off);
        float4 v1 = *(const float4*)(src + off + 4);
        uint4 o;
        o.x = pack_h2(v0.x, v0.y); o.y = pack_h2(v0.z, v0.w);
        o.z = pack_h2(v1.x, v1.y); o.w = pack_h2(v1.z, v1.w);
        *(uint4*)(h_w + E) = o;
    } else {
        int i = (int)(((size_t)blockIdx.x * 256 + threadIdx.x) - TOTW / 8);
        if (i < 3 * DIM) {
            int sel = i / DIM, off = i - sel * DIM;
            const float* src = (sel == 0) ? bq : (sel == 1) ? bk : bv;
            g_bqkv[i] = src[off];
        }
    }
}

// Prep B: adjacency bitmask
static constexpr int MASK_BLOCKS = (BATCH * SEQ * 8) / 256;   // 512
__global__ __launch_bounds__(256) void prep_mask(const int* __restrict__ adj)
{
    int idx = blockIdx.x * 256 + threadIdx.x;
    const int* src = adj + (size_t)idx * 64;
    unsigned long long m = 0;
    #pragma unroll
    for (int i = 0; i < 16; i++) {
        int4 a = ((const int4*)src)[i];
        m |= ((unsigned long long)(a.x != 0)) << (4 * i + 0);
        m |= ((unsigned long long)(a.y != 0)) << (4 * i + 1);
        m |= ((unsigned long long)(a.z != 0)) << (4 * i + 2);
        m |= ((unsigned long long)(a.w != 0)) << (4 * i + 3);
    }
    g_mask[idx] = m;
}

// ---------------------------------------------------------------------------
// fp16 mma GEMM — big warp tile + LONG K-STAGE:
// CTA 128x128, 4 warps (2x2), warp tile 64x64, 128 threads, 256 regs.
// K-stage 64, 3 stages, CP_WAIT(1), issue-after-compute.
// Per stage per warp: 32 ldsm : 128 MMA; barriers per CTA halved vs R13.
// smem: A [3][128][72]h (144 B pitch), B [3][64][136]h (272 B pitch) = 105 KB
// EPI 0: +bias, permuted half store; Nc=2304 routes to Cq/Ck/Cv [B,H,N,64]
// EPI 1: +bias +res(fp32), fp32 store
// EPI 2: +bias, exact GELU, half store
// ---------------------------------------------------------------------------
static constexpr int GST  = 3;
static constexpr int A_ST = 128 * 72;    // halves per A stage (9216)
static constexpr int B_ST = 64 * 136;    // halves per B stage (8704)
static constexpr int GEMM_SMEM = GST * (A_ST + B_ST) * 2;   // 107520 B

template <int EPI>
__global__ __launch_bounds__(128, 2) void hgemm(
    const __half* __restrict__ A, const __half* __restrict__ W,
    const float* __restrict__ bias, const float* __restrict__ res,
    void* __restrict__ Cv, void* __restrict__ Cv2, void* __restrict__ Cv3,
    int Nc, int K)
{
    extern __shared__ __half hsm[];
    const uint32_t baseA = smem_u32(hsm);
    const uint32_t baseB = smem_u32(hsm + GST * A_ST);

    const int tid  = threadIdx.x;
    const int wid  = tid >> 5, lane = tid & 31;
    const int grp  = lane >> 2, tid4 = lane & 3;
    const int wm   = (wid >> 1) * 64;       // 0 or 64
    const int wn   = (wid & 1) * 64;        // 0 or 64
    const int row0 = blockIdx.y * 128;
    const int col0 = blockIdx.x * 128;

    float acc[4][8][4];
    #pragma unroll
    for (int t = 0; t < 4; t++)
        #pragma unroll
        for (int j = 0; j < 8; j++)
            #pragma unroll
            for (int r = 0; r < 4; r++) acc[t][j][r] = 0.f;

    const int nst = K >> 6;   // K-stage 64

    // Per stage: A 128x64h (8 chunks/thread), B 64x128h (8 chunks/thread)
    auto issue = [&](int s) {
        const int b = s % GST;
        const int k0 = s << 6;
        #pragma unroll
        for (int it = 0; it < 8; it++) {
            int id = tid + it * 128;
            int ar = id >> 3, ac = (id & 7) << 3;
            CP_ASYNC16(baseA + (b * A_ST + ar * 72 + ac) * 2,
                       A + (size_t)(row0 + ar) * K + k0 + ac);
            int br = id >> 4, bc = (id & 15) << 3;
            CP_ASYNC16(baseB + (b * B_ST + br * 136 + bc) * 2,
                       W + (size_t)(k0 + br) * Nc + col0 + bc);
        }
    };

    issue(0); CP_COMMIT();
    issue(1); CP_COMMIT();

    const int a_row = (lane & 15), a_k8 = (lane >> 4) << 3;
    const int b_k   = (lane & 15), b_n8 = (lane >> 4) << 3;

    for (int st = 0; st < nst; st++) {
        CP_WAIT(1);
        __syncthreads();

        const uint32_t ab = baseA + (st % GST) * A_ST * 2;
        const uint32_t bb = baseB + (st % GST) * B_ST * 2;

        #pragma unroll
        for (int s = 0; s < 4; s++) {            // 4 x k16 sub-steps
            uint32_t af[4][4];
            #pragma unroll
            for (int t = 0; t < 4; t++) {
                uint32_t ad = ab + ((wm + t * 16 + a_row) * 72 + s * 16 + a_k8) * 2;
                LDSM4(af[t][0], af[t][1], af[t][2], af[t][3], ad);
            }
            uint32_t bfr[4][4];
            #pragma unroll
            for (int g = 0; g < 4; g++) {
                uint32_t bd = bb + ((s * 16 + b_k) * 136 + wn + g * 16 + b_n8) * 2;
                LDSM4T(bfr[g][0], bfr[g][1], bfr[g][2], bfr[g][3], bd);
            }
            #pragma unroll
            for (int t = 0; t < 4; t++)
                #pragma unroll
                for (int j = 0; j < 8; j++)
                    mma_f16(acc[t][j], af[t][0], af[t][1], af[t][2], af[t][3],
                            bfr[j >> 1][(j & 1) * 2], bfr[j >> 1][(j & 1) * 2 + 1]);
        }
        // Issue next stage AFTER compute (R7/R13 proven ordering).
        if (st + 2 < nst) issue(st + 2);
        CP_COMMIT();
    }

    // Epilogue (rows wm+t*16+grp / +8, cols wn+j*8+tid4*2)
    #pragma unroll
    for (int t = 0; t < 4; t++) {
        int r_lo = row0 + wm + t * 16 + grp;
        int r_hi = r_lo + 8;
        #pragma unroll
        for (int j = 0; j < 8; j++) {
            int c = col0 + wn + j * 8 + tid4 * 2;
            float b0 = bias[c], b1 = bias[c + 1];
            float v00 = acc[t][j][0] + b0, v01 = acc[t][j][1] + b1;
            float v10 = acc[t][j][2] + b0, v11 = acc[t][j][3] + b1;
            if (EPI == 0) {
                int sel = c / DIM;
                int cc  = c - sel * DIM;
                __half* C = (sel == 0) ? (__half*)Cv : (sel == 1) ? (__half*)Cv2
                                                                  : (__half*)Cv3;
                int h = cc >> 6, d = cc & 63;
                int blo = r_lo >> 9, nlo = r_lo & 511;
                int bhi = r_hi >> 9, nhi = r_hi & 511;
                *(__half2*)(C + (((size_t)(blo * HEADS + h)) * SEQ + nlo) * HDIM + d) =
                    __floats2half2_rn(v00, v01);
                *(__half2*)(C + (((size_t)(bhi * HEADS + h)) * SEQ + nhi) * HDIM + d) =
                    __floats2half2_rn(v10, v11);
            } else if (EPI == 1) {
                float* C = (float*)Cv;
                const float2 r0 = *(const float2*)(res + (size_t)r_lo * Nc + c);
                const float2 r1 = *(const float2*)(res + (size_t)r_hi * Nc + c);
                *(float2*)(C + (size_t)r_lo * Nc + c) = make_float2(v00 + r0.x, v01 + r0.y);
                *(float2*)(C + (size_t)r_hi * Nc + c) = make_float2(v10 + r1.x, v11 + r1.y);
            } else {
                __half* C = (__half*)Cv;
                const float is2 = 0.70710678118654752f;
                v00 = 0.5f * v00 * (1.0f + erff(v00 * is2));
                v01 = 0.5f * v01 * (1.0f + erff(v01 * is2));
                v10 = 0.5f * v10 * (1.0f + erff(v10 * is2));
                v11 = 0.5f * v11 * (1.0f + erff(v11 * is2));
                *(__half2*)(C + (size_t)r_lo * Nc + c) = __floats2half2_rn(v00, v01);
                *(__half2*)(C + (size_t)r_hi * Nc + c) = __floats2half2_rn(v10, v11);
            }
        }
    }
}

// ---------------------------------------------------------------------------
// LayerNorm: fp32 in -> half out. 192 threads, float4 path.
// ---------------------------------------------------------------------------
__global__ __launch_bounds__(192) void ln_kernel(
    const float* __restrict__ x, const float* __restrict__ g,
    const float* __restrict__ b, __half* __restrict__ y)
{
    int row = blockIdx.x;
    int tid = threadIdx.x;
    float4 v = *(const float4*)(x + (size_t)row * DIM + tid * 4);
    float s  = v.x + v.y + v.z + v.w;
    float ss = v.x * v.x + v.y * v.y + v.z * v.z + v.w * v.w;
    #pragma unroll
    for (int o = 16; o > 0; o >>= 1) {
        s  += __shfl_xor_sync(0xffffffffu, s, o);
        ss += __shfl_xor_sync(0xffffffffu, ss, o);
    }
    __shared__ float sh_s[6], sh_ss[6];
    int w = tid >> 5, l = tid & 31;
    if (l == 0) { sh_s[w] = s; sh_ss[w] = ss; }
    __syncthreads();
    float ts = 0.f, tss = 0.f;
    #pragma unroll
    for (int i = 0; i < 6; i++) { ts += sh_s[i]; tss += sh_ss[i]; }
    float mean = ts * (1.0f / DIM);
    float var  = tss * (1.0f / DIM) - mean * mean;
    float inv  = rsqrtf(var + 1e-5f);
    float4 gg = *(const float4*)(g + tid * 4);
    float4 bb = *(const float4*)(b + tid * 4);
    __half2 o0 = __floats2half2_rn((v.x - mean) * inv * gg.x + bb.x,
                                   (v.y - mean) * inv * gg.y + bb.y);
    __half2 o1 = __floats2half2_rn((v.z - mean) * inv * gg.z + bb.z,
                                   (v.w - mean) * inv * gg.w + bb.w);
    __half2* yr = (__half2*)(y + (size_t)row * DIM + tid * 4);
    yr[0] = o0; yr[1] = o1;
}

// ---------------------------------------------------------------------------
// Flash attention (R12/R13 version: ex2.approx.f16x2 softmax, MMA l-sum).
// ---------------------------------------------------------------------------
static constexpr int QP   = 72;
static constexpr int O_Q  = 0;
static constexpr int O_K  = 128 * QP;
static constexpr int O_V  = O_K + 2 * 64 * QP;
static constexpr int ATT_SMEM = (O_V + 2 * 64 * QP) * 2;   // 55296 B

__global__ __launch_bounds__(256, 2) void attn_flash(
    const __half* __restrict__ q, const __half* __restrict__ kin,
    const __half* __restrict__ v, const unsigned long long* __restrict__ mask,
    __half* __restrict__ out)
{
    extern __shared__ __half hsm[];
    const uint32_t baseQ = smem_u32(hsm + O_Q);
    const uint32_t baseK = smem_u32(hsm + O_K);
    const uint32_t baseV = smem_u32(hsm + O_V);

    const int tid  = threadIdx.x;
    const int wid  = tid >> 5, lane = tid & 31;
    const int grp  = lane >> 2, tid4 = lane & 3;
    const int m0   = wid * 16;
    const int bh   = blockIdx.y;
    const int bb   = bh / HEADS, hh = bh % HEADS;
    const int q0   = blockIdx.x * 128;

    const __half* qb = q   + (size_t)bh * SEQ * HDIM + (size_t)q0 * HDIM;
    const __half* kb = kin + (size_t)bh * SEQ * HDIM;
    const __half* vb = v   + (size_t)bh * SEQ * HDIM;

    #pragma unroll
    for (int it = 0; it < 4; it++) {
        int id = tid + it * 256;
        int r = id >> 3, c = (id & 7) << 3;
        CP_ASYNC16(baseQ + (r * QP + c) * 2, qb + r * HDIM + c);
    }
    #pragma unroll
    for (int it = 0; it < 2; it++) {
        int id = tid + it * 256;
        int r = id >> 3, c = (id & 7) << 3;
        CP_ASYNC16(baseK + (r * QP + c) * 2, kb + r * HDIM + c);
        CP_ASYNC16(baseV + (r * QP + c) * 2, vb + r * HDIM + c);
    }
    CP_COMMIT();

    float m_run0 = -1e4f, m_run1 = -1e4f;
    float lacc[4] = {0.f, 0.f, 0.f, 0.f};
    float acc[8][4];
    #pragma unroll
    for (int j = 0; j < 8; j++)
        #pragma unroll
        for (int r = 0; r < 4; r++) acc[j][r] = 0.f;

    uint32_t qf[4][4];
    const float scale = 0.125f;
    const float L2E   = 1.44269504f;
    const uint32_t ONES = 0x3C003C00u;

    const int l15 = lane & 15, l7 = lane & 7;
    const int hi8 = (lane >> 4) << 3;
    const int b8  = ((lane >> 3) & 1) << 3;

    for (int kt = 0; kt < 8; kt++) {
        CP_WAIT(0);
        __syncthreads();
        if (kt + 1 < 8) {
            int bufn = ((kt + 1) & 1) * 64 * QP * 2;
            const __half* kn = kb + (size_t)(kt + 1) * 64 * HDIM;
            const __half* vn = vb + (size_t)(kt + 1) * 64 * HDIM;
            #pragma unroll
            for (int it = 0; it < 2; it++) {
                int id = tid + it * 256;
                int r = id >> 3, c = (id & 7) << 3;
                CP_ASYNC16(baseK + bufn + (r * QP + c) * 2, kn + r * HDIM + c);
                CP_ASYNC16(baseV + bufn + (r * QP + c) * 2, vn + r * HDIM + c);
            }
        }
        CP_COMMIT();

        if (kt == 0) {
            #pragma unroll
            for (int ks = 0; ks < 4; ks++) {
                uint32_t ad = baseQ + ((m0 + l15) * QP + ks * 16 + hi8) * 2;
                LDSM4(qf[ks][0], qf[ks][1], qf[ks][2], qf[ks][3], ad);
            }
        }

        const uint32_t kbuf = baseK + (kt & 1) * 64 * QP * 2;
        const uint32_t vbuf = baseV + (kt & 1) * 64 * QP * 2;

        float sc[8][4];
        #pragma unroll
        for (int j = 0; j < 8; j++)
            #pragma unroll
            for (int r = 0; r < 4; r++) sc[j][r] = 0.f;

        #pragma unroll
        for (int ks = 0; ks < 4; ks++) {
            #pragma unroll
            for (int g = 0; g < 4; g++) {
                uint32_t kd = kbuf + ((g * 16 + l7 + hi8) * QP + ks * 16 + b8) * 2;
                uint32_t k0r, k1r, k2r, k3r;
                LDSM4(k0r, k1r, k2r, k3r, kd);
                mma_f16(sc[2 * g],     qf[ks][0], qf[ks][1], qf[ks][2], qf[ks][3], k0r, k1r);
                mma_f16(sc[2 * g + 1], qf[ks][0], qf[ks][1], qf[ks][2], qf[ks][3], k2r, k3r);
            }
        }

        unsigned long long mlo = mask[((size_t)bb * SEQ + q0 + m0 + grp)     * 8 + kt];
        unsigned long long mhi = mask[((size_t)bb * SEQ + q0 + m0 + grp + 8) * 8 + kt];
        float mx0 = -1e30f, mx1 = -1e30f;
        #pragma unroll
        for (int j = 0; j < 8; j++) {
            int c0 = j * 8 + tid4 * 2;
            sc[j][0] = ((mlo >> c0) & 1)       ? sc[j][0] * scale : -1e30f;
            sc[j][1] = ((mlo >> (c0 + 1)) & 1) ? sc[j][1] * scale : -1e30f;
            sc[j][2] = ((mhi >> c0) & 1)       ? sc[j][2] * scale : -1e30f;
            sc[j][3] = ((mhi >> (c0 + 1)) & 1) ? sc[j][3] * scale : -1e30f;
            mx0 = fmaxf(mx0, fmaxf(sc[j][0], sc[j][1]));
            mx1 = fmaxf(mx1, fmaxf(sc[j][2], sc[j][3]));
        }
        mx0 = fmaxf(mx0, __shfl_xor_sync(0xffffffffu, mx0, 1));
        mx0 = fmaxf(mx0, __shfl_xor_sync(0xffffffffu, mx0, 2));
        mx1 = fmaxf(mx1, __shfl_xor_sync(0xffffffffu, mx1, 1));
        mx1 = fmaxf(mx1, __shfl_xor_sync(0xffffffffu, mx1, 2));

        float mn0 = fmaxf(m_run0, mx0), mn1 = fmaxf(m_run1, mx1);
        float f0 = __expf(m_run0 - mn0), f1 = __expf(m_run1 - mn1);
        m_run0 = mn0; m_run1 = mn1;

        uint32_t pl[8], ph[8];
        #pragma unroll
        for (int j = 0; j < 8; j++) {
            pl[j] = ex2_h2(pack_h2((sc[j][0] - mn0) * L2E, (sc[j][1] - mn0) * L2E));
            ph[j] = ex2_h2(pack_h2((sc[j][2] - mn1) * L2E, (sc[j][3] - mn1) * L2E));
        }

        #pragma unroll
        for (int j = 0; j < 8; j++) {
            acc[j][0] *= f0; acc[j][1] *= f0;
            acc[j][2] *= f1; acc[j][3] *= f1;
        }
        lacc[0] *= f0; lacc[1] *= f0;
        lacc[2] *= f1; lacc[3] *= f1;

        #pragma unroll
        for (int s = 0; s < 4; s++) {
            uint32_t a0 = pl[2 * s], a1 = ph[2 * s], a2 = pl[2 * s + 1], a3 = ph[2 * s + 1];
            mma_f16(lacc, a0, a1, a2, a3, ONES, ONES);
            #pragma unroll
            for (int g = 0; g < 4; g++) {
                uint32_t vd = vbuf + ((s * 16 + l15) * QP + g * 16 + hi8) * 2;
                uint32_t v0r, v1r, v2r, v3r;
                LDSM4T(v0r, v1r, v2r, v3r, vd);
                mma_f16(acc[2 * g],     a0, a1, a2, a3, v0r, v1r);
                mma_f16(acc[2 * g + 1], a0, a1, a2, a3, v2r, v3r);
            }
        }
    }

    const float inv0 = 1.0f / lacc[0];
    const float inv1 = 1.0f / lacc[2];
    const int rlo = q0 + m0 + grp, rhi = rlo + 8;
    #pragma unroll
    for (int j = 0; j < 8; j++) {
        int d = hh * HDIM + j * 8 + tid4 * 2;
        *(__half2*)(out + ((size_t)bb * SEQ + rlo) * DIM + d) =
            __floats2half2_rn(acc[j][0] * inv0, acc[j][1] * inv0);
        *(__half2*)(out + ((size_t)bb * SEQ + rhi) * DIM + d) =
            __floats2half2_rn(acc[j][2] * inv1, acc[j][3] * inv1);
    }
}

// ---------------------------------------------------------------------------
extern "C" void kernel_launch(void* const* d_in, const int* in_sizes, int n_in,
                              void* d_out, int out_size)
{
    const float* x   = (const float*)d_in[0];
    const int*   adj = (const int*)  d_in[1];
    const float* wq  = (const float*)d_in[2];
    const float* bq  = (const float*)d_in[3];
    const float* wk  = (const float*)d_in[4];
    const float* bk  = (const float*)d_in[5];
    const float* wv  = (const float*)d_in[6];
    const float* bv  = (const float*)d_in[7];
    const float* wo  = (const float*)d_in[8];
    const float* bo  = (const float*)d_in[9];
    const float* g1  = (const float*)d_in[10];
    const float* b1  = (const float*)d_in[11];
    const float* g2  = (const float*)d_in[12];
    const float* b2  = (const float*)d_in[13];
    const float* w1  = (const float*)d_in[14];
    const float* bf1 = (const float*)d_in[15];
    const float* w2  = (const float*)d_in[16];
    const float* bf2 = (const float*)d_in[17];
    float* out = (float*)d_out;

    __half *pln, *pq, *pk, *pv, *patt, *pgelu, *pw;
    float  *pout1, *pbqkv;
    unsigned long long* pmask;
    cudaGetSymbolAddress((void**)&pln,   h_ln);
    cudaGetSymbolAddress((void**)&pq,    h_q);
    cudaGetSymbolAddress((void**)&pk,    h_k);
    cudaGetSymbolAddress((void**)&pv,    h_v);
    cudaGetSymbolAddress((void**)&patt,  h_att);
    cudaGetSymbolAddress((void**)&pgelu, h_gelu);
    cudaGetSymbolAddress((void**)&pw,    h_w);
    cudaGetSymbolAddress((void**)&pout1, g_out1);
    cudaGetSymbolAddress((void**)&pbqkv, g_bqkv);
    cudaGetSymbolAddress((void**)&pmask, g_mask);

    __half* wqkvH = pw;
    __half* woH   = pw + 3 * WELEM;
    __half* w1H   = pw + 4 * WELEM;
    __half* w2H   = pw + 4 * WELEM + FELEM;

    static cudaStream_t sSide = nullptr;
    static cudaEvent_t evRoot = nullptr, evW = nullptr, evM = nullptr;
    static bool attr_set = false;
    if (!attr_set) {
        cudaFuncSetAttribute(attn_flash, cudaFuncAttributeMaxDynamicSharedMemorySize, ATT_SMEM);
        cudaFuncSetAttribute(hgemm<0>, cudaFuncAttributeMaxDynamicSharedMemorySize, GEMM_SMEM);
        cudaFuncSetAttribute(hgemm<1>, cudaFuncAttributeMaxDynamicSharedMemorySize, GEMM_SMEM);
        cudaFuncSetAttribute(hgemm<2>, cudaFuncAttributeMaxDynamicSharedMemorySize, GEMM_SMEM);
        cudaStreamCreateWithFlags(&sSide, cudaStreamNonBlocking);
        cudaEventCreateWithFlags(&evRoot, cudaEventDisableTiming);
        cudaEventCreateWithFlags(&evW,    cudaEventDisableTiming);
        cudaEventCreateWithFlags(&evM,    cudaEventDisableTiming);
        attr_set = true;
    }

    // Fork: prep on side stream, LN1 on main (fork-join capturable)
    cudaEventRecord(evRoot, 0);
    cudaStreamWaitEvent(sSide, evRoot, 0);
    prep_weights<<<PREPW_BLOCKS, 256, 0, sSide>>>(wq, wk, wv, wo, w1, w2, bq, bk, bv);
    cudaEventRecord(evW, sSide);
    prep_mask<<<MASK_BLOCKS, 256, 0, sSide>>>(adj);
    cudaEventRecord(evM, sSide);

    ln_kernel<<<MROWS, 192>>>(x, g1, b1, pln);

    cudaStreamWaitEvent(0, evW, 0);

    // Fused QKV projection (N=2304)
    dim3 gqkv(3 * DIM / 128, MROWS / 128);
    hgemm<0><<<gqkv, 128, GEMM_SMEM>>>(pln, wqkvH, pbqkv, nullptr,
                                       pq, pk, pv, 3 * DIM, DIM);

    cudaStreamWaitEvent(0, evM, 0);

    // Flash attention
    attn_flash<<<dim3(SEQ / 128, BATCH * HEADS), 256, ATT_SMEM>>>(pq, pk, pv, pmask, patt);

    // Output projection + bias + residual(x)
    dim3 g768(DIM / 128, MROWS / 128);
    hgemm<1><<<g768, 128, GEMM_SMEM>>>(patt, woH, bo, x, pout1, nullptr, nullptr, DIM, DIM);

    // LN2
    ln_kernel<<<MROWS, 192>>>(pout1, g2, b2, pln);

    // FFN1 + GELU
    dim3 g3072(DFF / 128, MROWS / 128);
    hgemm<2><<<g3072, 128, GEMM_SMEM>>>(pln, w1H, bf1, nullptr, pgelu, nullptr, nullptr, DFF, DIM);

    // FFN2 + bias + residual(out1) -> final output
    hgemm<1><<<g768, 128, GEMM_SMEM>>>(pgelu, w2H, bf2, pout1, out, nullptr, nullptr, DIM, DFF);
}

// round 16
// speedup vs baseline: 1.0425x; 1.0425x over previous
#include <cuda_runtime.h>
#include <cuda_fp16.h>
#include <math.h>
#include <stdint.h>

// Problem constants
static constexpr int BATCH = 32;
static constexpr int SEQ   = 512;
static constexpr int DIM   = 768;
static constexpr int HEADS = 12;
static constexpr int HDIM  = 64;
static constexpr int MROWS = BATCH * SEQ;   // 16384
static constexpr int DFF   = 3072;

// Scratch (device globals — allocation-free rule)
__device__ __half h_ln  [MROWS * DIM];
__device__ __half h_q   [MROWS * DIM];
__device__ __half h_k   [MROWS * DIM];
__device__ __half h_v   [MROWS * DIM];
__device__ __half h_att [MROWS * DIM];
__device__ __half h_gelu[MROWS * DFF];
__device__ float  g_out1[MROWS * DIM];
__device__ __half h_w   [4 * DIM * DIM + 2 * DIM * DFF];
__device__ float  g_bqkv[3 * DIM];
__device__ unsigned long long g_mask[BATCH * SEQ * 8];

// ---------------------------------------------------------------------------
// Helpers
// ---------------------------------------------------------------------------
__device__ __forceinline__ uint32_t smem_u32(const void* p) {
    uint32_t a;
    asm("{ .reg .u64 t; cvta.to.shared.u64 t, %1; cvt.u32.u64 %0, t; }" : "=r"(a) : "l"(p));
    return a;
}
__device__ __forceinline__ uint32_t pack_h2(float a, float b) {
    __half2 t = __floats2half2_rn(a, b);
    return *reinterpret_cast<uint32_t*>(&t);
}
__device__ __forceinline__ uint32_t ex2_h2(uint32_t t) {
    uint32_t r;
    asm("ex2.approx.f16x2 %0, %1;" : "=r"(r) : "r"(t));
    return r;
}
__device__ __forceinline__ void mma_f16(float* c, uint32_t a0, uint32_t a1,
                                        uint32_t a2, uint32_t a3,
                                        uint32_t b0, uint32_t b1) {
    asm volatile(
        "mma.sync.aligned.m16n8k16.row.col.f32.f16.f16.f32 "
        "{%0,%1,%2,%3}, {%4,%5,%6,%7}, {%8,%9}, {%0,%1,%2,%3};"
        : "+f"(c[0]), "+f"(c[1]), "+f"(c[2]), "+f"(c[3])
        : "r"(a0), "r"(a1), "r"(a2), "r"(a3), "r"(b0), "r"(b1));
}
#define LDSM4(r0, r1, r2, r3, addr)                                            \
    asm volatile("ldmatrix.sync.aligned.m8n8.x4.shared.b16 {%0,%1,%2,%3}, [%4];" \
        : "=r"(r0), "=r"(r1), "=r"(r2), "=r"(r3) : "r"(addr))
#define LDSM4T(r0, r1, r2, r3, addr)                                           \
    asm volatile("ldmatrix.sync.aligned.m8n8.x4.trans.shared.b16 {%0,%1,%2,%3}, [%4];" \
        : "=r"(r0), "=r"(r1), "=r"(r2), "=r"(r3) : "r"(addr))
#define CP_ASYNC16(dst, src) \
    asm volatile("cp.async.cg.shared.global [%0], [%1], 16;" :: "r"(dst), "l"(src))
#define CP_COMMIT()  asm volatile("cp.async.commit_group;" ::: "memory")
#define CP_WAIT(N)   asm volatile("cp.async.wait_group %0;" :: "n"(N) : "memory")

// ---------------------------------------------------------------------------
// Prep A: weights fp32->fp16. Wq/Wk/Wv packed FUSED: h_w[k*2304 + c].
// ---------------------------------------------------------------------------
static constexpr int WELEM = DIM * DIM;               // 589824
static constexpr int FELEM = DIM * DFF;               // 2359296
static constexpr int TOTW  = 4 * WELEM + 2 * FELEM;
static constexpr int PREPW_BLOCKS = TOTW / (256 * 8) + 2;

__global__ __launch_bounds__(256) void prep_weights(
    const float* __restrict__ wq, const float* __restrict__ wk,
    const float* __restrict__ wv, const float* __restrict__ wo,
    const float* __restrict__ w1, const float* __restrict__ w2,
    const float* __restrict__ bq, const float* __restrict__ bk,
    const float* __restrict__ bv)
{
    size_t E = ((size_t)blockIdx.x * 256 + threadIdx.x) * 8;
    if (E < (size_t)TOTW) {
        const float* src; size_t off;
        if (E < 3 * (size_t)WELEM) {
            size_t k = E / 2304, c = E - k * 2304;
            int sel = (int)(c / DIM);
            src = (sel == 0) ? wq : (sel == 1) ? wk : wv;
            off = k * DIM + (c - (size_t)sel * DIM);
        } else if (E < 4 * (size_t)WELEM) { src = wo; off = E - 3 * (size_t)WELEM; }
        else if (E < 4 * (size_t)WELEM + FELEM) { src = w1; off = E - 4 * (size_t)WELEM; }
        else { src = w2; off = E - 4 * (size_t)WELEM - FELEM; }
        float4 v0 = *(const float4*)(src + off);
        float4 v1 = *(const float4*)(src + off + 4);
        uint4 o;
        o.x = pack_h2(v0.x, v0.y); o.y = pack_h2(v0.z, v0.w);
        o.z = pack_h2(v1.x, v1.y); o.w = pack_h2(v1.z, v1.w);
        *(uint4*)(h_w + E) = o;
    } else {
        int i = (int)(((size_t)blockIdx.x * 256 + threadIdx.x) - TOTW / 8);
        if (i < 3 * DIM) {
            int sel = i / DIM, off = i - sel * DIM;
            const float* src = (sel == 0) ? bq : (sel == 1) ? bk : bv;
            g_bqkv[i] = src[off];
        }
    }
}

// Prep B: adjacency bitmask
static constexpr int MASK_BLOCKS = (BATCH * SEQ * 8) / 256;   // 512
__global__ __launch_bounds__(256) void prep_mask(const int* __restrict__ adj)
{
    int idx = blockIdx.x * 256 + threadIdx.x;
    const int* src = adj + (size_t)idx * 64;
    unsigned long long m = 0;
    #pragma unroll
    for (int i = 0; i < 16; i++) {
        int4 a = ((const int4*)src)[i];
        m |= ((unsigned long long)(a.x != 0)) << (4 * i + 0);
        m |= ((unsigned long long)(a.y != 0)) << (4 * i + 1);
        m |= ((unsigned long long)(a.z != 0)) << (4 * i + 2);
        m |= ((unsigned long long)(a.w != 0)) << (4 * i + 3);
    }
    g_mask[idx] = m;
}

// ---------------------------------------------------------------------------
// fp16 mma GEMM — R14 proven core (best: 865 us): CTA 128x128, 4 warps (2x2),
// warp tile 64x64, 128 threads, 256 regs. 4-stage K32 cp.async, CP_WAIT(2).
// NEW in R15: next-stage cp.async issue INTERLEAVED into the MMA burst
// (half after sub-step-0 fragment loads, half + commit after sub-step-0 MMAs).
// Buffer (st+3)&3 was consumed in iter st-1; this iter's barrier protects it.
// EPI 0: +bias, permuted half store; Nc=2304 routes to Cq/Ck/Cv [B,H,N,64]
// EPI 1: +bias +res(fp32), fp32 store
// EPI 2: +bias, exact GELU, half store
// ---------------------------------------------------------------------------
static constexpr int GST  = 4;
static constexpr int A_ST = 128 * 40;
static constexpr int B_ST = 32 * 136;
static constexpr int GEMM_SMEM = GST * (A_ST + B_ST) * 2;   // 75776 B

template <int EPI>
__global__ __launch_bounds__(128, 2) void hgemm(
    const __half* __restrict__ A, const __half* __restrict__ W,
    const float* __restrict__ bias, const float* __restrict__ res,
    void* __restrict__ Cv, void* __restrict__ Cv2, void* __restrict__ Cv3,
    int Nc, int K)
{
    extern __shared__ __half hsm[];
    const uint32_t baseA = smem_u32(hsm);
    const uint32_t baseB = smem_u32(hsm + GST * A_ST);

    const int tid  = threadIdx.x;
    const int wid  = tid >> 5, lane = tid & 31;
    const int grp  = lane >> 2, tid4 = lane & 3;
    const int wm   = (wid >> 1) * 64;       // 0 or 64
    const int wn   = (wid & 1) * 64;        // 0 or 64
    const int row0 = blockIdx.y * 128;
    const int col0 = blockIdx.x * 128;

    float acc[4][8][4];
    #pragma unroll
    for (int t = 0; t < 4; t++)
        #pragma unroll
        for (int j = 0; j < 8; j++)
            #pragma unroll
            for (int r = 0; r < 4; r++) acc[t][j][r] = 0.f;

    const int nst = K >> 5;   // K-stage 32

    // Stage staging: A 128x32h + B 32x128h; 4 (A,B) chunk-pairs per thread.
    // issue_half(s, 0) = chunk-pairs 0,1 ; issue_half(s, 1) = chunk-pairs 2,3.
    auto issue_half = [&](int s, int half) {
        const int b = s & 3;
        const int k0 = s << 5;
        #pragma unroll
        for (int it = half * 2; it < half * 2 + 2; it++) {
            int id = tid + it * 128;
            int ar = id >> 2, ac = (id & 3) << 3;
            CP_ASYNC16(baseA + (b * A_ST + ar * 40 + ac) * 2,
                       A + (size_t)(row0 + ar) * K + k0 + ac);
            int br = id >> 4, bc = (id & 15) << 3;
            CP_ASYNC16(baseB + (b * B_ST + br * 136 + bc) * 2,
                       W + (size_t)(k0 + br) * Nc + col0 + bc);
        }
    };
    auto issue = [&](int s) { issue_half(s, 0); issue_half(s, 1); };

    issue(0); CP_COMMIT();
    issue(1); CP_COMMIT();
    issue(2); CP_COMMIT();

    const int a_row = (lane & 15), a_k8 = (lane >> 4) << 3;
    const int b_k   = (lane & 15), b_n8 = (lane >> 4) << 3;

    for (int st = 0; st < nst; st++) {
        CP_WAIT(2);
        __syncthreads();

        const uint32_t ab = baseA + (st & 3) * A_ST * 2;
        const uint32_t bb = baseB + (st & 3) * B_ST * 2;
        const bool more = (st + 3 < nst);

        // ---- sub-step 0: fragment loads ----
        uint32_t af0[4][4], bf0[4][4];
        #pragma unroll
        for (int t = 0; t < 4; t++) {
            uint32_t ad = ab + ((wm + t * 16 + a_row) * 40 + a_k8) * 2;
            LDSM4(af0[t][0], af0[t][1], af0[t][2], af0[t][3], ad);
        }
        #pragma unroll
        for (int g = 0; g < 4; g++) {
            uint32_t bd = bb + (b_k * 136 + wn + g * 16 + b_n8) * 2;
            LDSM4T(bf0[g][0], bf0[g][1], bf0[g][2], bf0[g][3], bd);
        }
        // interleave: first half of next-stage staging under the MMA burst
        if (more) issue_half(st + 3, 0);

        #pragma unroll
        for (int t = 0; t < 4; t++)
            #pragma unroll
            for (int j = 0; j < 8; j++)
                mma_f16(acc[t][j], af0[t][0], af0[t][1], af0[t][2], af0[t][3],
                        bf0[j >> 1][(j & 1) * 2], bf0[j >> 1][(j & 1) * 2 + 1]);

        // interleave: second half + commit
        if (more) issue_half(st + 3, 1);
        CP_COMMIT();

        // ---- sub-step 1 ----
        uint32_t af1[4][4], bf1r[4][4];
        #pragma unroll
        for (int t = 0; t < 4; t++) {
            uint32_t ad = ab + ((wm + t * 16 + a_row) * 40 + 16 + a_k8) * 2;
            LDSM4(af1[t][0], af1[t][1], af1[t][2], af1[t][3], ad);
        }
        #pragma unroll
        for (int g = 0; g < 4; g++) {
            uint32_t bd = bb + ((16 + b_k) * 136 + wn + g * 16 + b_n8) * 2;
            LDSM4T(bf1r[g][0], bf1r[g][1], bf1r[g][2], bf1r[g][3], bd);
        }
        #pragma unroll
        for (int t = 0; t < 4; t++)
            #pragma unroll
            for (int j = 0; j < 8; j++)
                mma_f16(acc[t][j], af1[t][0], af1[t][1], af1[t][2], af1[t][3],
                        bf1r[j >> 1][(j & 1) * 2], bf1r[j >> 1][(j & 1) * 2 + 1]);
    }

    // Epilogue (rows wm+t*16+grp / +8, cols wn+j*8+tid4*2)
    #pragma unroll
    for (int t = 0; t < 4; t++) {
        int r_lo = row0 + wm + t * 16 + grp;
        int r_hi = r_lo + 8;
        #pragma unroll
        for (int j = 0; j < 8; j++) {
            int c = col0 + wn + j * 8 + tid4 * 2;
            float b0 = bias[c], b1 = bias[c + 1];
            float v00 = acc[t][j][0] + b0, v01 = acc[t][j][1] + b1;
            float v10 = acc[t][j][2] + b0, v11 = acc[t][j][3] + b1;
            if (EPI == 0) {
                int sel = c / DIM;
                int cc  = c - sel * DIM;
                __half* C = (sel == 0) ? (__half*)Cv : (sel == 1) ? (__half*)Cv2
                                                                  : (__half*)Cv3;
                int h = cc >> 6, d = cc & 63;
                int blo = r_lo >> 9, nlo = r_lo & 511;
                int bhi = r_hi >> 9, nhi = r_hi & 511;
                *(__half2*)(C + (((size_t)(blo * HEADS + h)) * SEQ + nlo) * HDIM + d) =
                    __floats2half2_rn(v00, v01);
                *(__half2*)(C + (((size_t)(bhi * HEADS + h)) * SEQ + nhi) * HDIM + d) =
                    __floats2half2_rn(v10, v11);
            } else if (EPI == 1) {
                float* C = (float*)Cv;
                const float2 r0 = *(const float2*)(res + (size_t)r_lo * Nc + c);
                const float2 r1 = *(const float2*)(res + (size_t)r_hi * Nc + c);
                *(float2*)(C + (size_t)r_lo * Nc + c) = make_float2(v00 + r0.x, v01 + r0.y);
                *(float2*)(C + (size_t)r_hi * Nc + c) = make_float2(v10 + r1.x, v11 + r1.y);
            } else {
                __half* C = (__half*)Cv;
                const float is2 = 0.70710678118654752f;
                v00 = 0.5f * v00 * (1.0f + erff(v00 * is2));
                v01 = 0.5f * v01 * (1.0f + erff(v01 * is2));
                v10 = 0.5f * v10 * (1.0f + erff(v10 * is2));
                v11 = 0.5f * v11 * (1.0f + erff(v11 * is2));
                *(__half2*)(C + (size_t)r_lo * Nc + c) = __floats2half2_rn(v00, v01);
                *(__half2*)(C + (size_t)r_hi * Nc + c) = __floats2half2_rn(v10, v11);
            }
        }
    }
}

// ---------------------------------------------------------------------------
// LayerNorm: fp32 in -> half out. 192 threads, float4 path.
// ---------------------------------------------------------------------------
__global__ __launch_bounds__(192) void ln_kernel(
    const float* __restrict__ x, const float* __restrict__ g,
    const float* __restrict__ b, __half* __restrict__ y)
{
    int row = blockIdx.x;
    int tid = threadIdx.x;
    float4 v = *(const float4*)(x + (size_t)row * DIM + tid * 4);
    float s  = v.x + v.y + v.z + v.w;
    float ss = v.x * v.x + v.y * v.y + v.z * v.z + v.w * v.w;
    #pragma unroll
    for (int o = 16; o > 0; o >>= 1) {
        s  += __shfl_xor_sync(0xffffffffu, s, o);
        ss += __shfl_xor_sync(0xffffffffu, ss, o);
    }
    __shared__ float sh_s[6], sh_ss[6];
    int w = tid >> 5, l = tid & 31;
    if (l == 0) { sh_s[w] = s; sh_ss[w] = ss; }
    __syncthreads();
    float ts = 0.f, tss = 0.f;
    #pragma unroll
    for (int i = 0; i < 6; i++) { ts += sh_s[i]; tss += sh_ss[i]; }
    float mean = ts * (1.0f / DIM);
    float var  = tss * (1.0f / DIM) - mean * mean;
    float inv  = rsqrtf(var + 1e-5f);
    float4 gg = *(const float4*)(g + tid * 4);
    float4 bb = *(const float4*)(b + tid * 4);
    __half2 o0 = __floats2half2_rn((v.x - mean) * inv * gg.x + bb.x,
                                   (v.y - mean) * inv * gg.y + bb.y);
    __half2 o1 = __floats2half2_rn((v.z - mean) * inv * gg.z + bb.z,
                                   (v.w - mean) * inv * gg.w + bb.w);
    __half2* yr = (__half2*)(y + (size_t)row * DIM + tid * 4);
    yr[0] = o0; yr[1] = o1;
}

// ---------------------------------------------------------------------------
// Flash attention (R12/R13 version: ex2.approx.f16x2 softmax, MMA l-sum).
// ---------------------------------------------------------------------------
static constexpr int QP   = 72;
static constexpr int O_Q  = 0;
static constexpr int O_K  = 128 * QP;
static constexpr int O_V  = O_K + 2 * 64 * QP;
static constexpr int ATT_SMEM = (O_V + 2 * 64 * QP) * 2;   // 55296 B

__global__ __launch_bounds__(256, 2) void attn_flash(
    const __half* __restrict__ q, const __half* __restrict__ kin,
    const __half* __restrict__ v, const unsigned long long* __restrict__ mask,
    __half* __restrict__ out)
{
    extern __shared__ __half hsm[];
    const uint32_t baseQ = smem_u32(hsm + O_Q);
    const uint32_t baseK = smem_u32(hsm + O_K);
    const uint32_t baseV = smem_u32(hsm + O_V);

    const int tid  = threadIdx.x;
    const int wid  = tid >> 5, lane = tid & 31;
    const int grp  = lane >> 2, tid4 = lane & 3;
    const int m0   = wid * 16;
    const int bh   = blockIdx.y;
    const int bb   = bh / HEADS, hh = bh % HEADS;
    const int q0   = blockIdx.x * 128;

    const __half* qb = q   + (size_t)bh * SEQ * HDIM + (size_t)q0 * HDIM;
    const __half* kb = kin + (size_t)bh * SEQ * HDIM;
    const __half* vb = v   + (size_t)bh * SEQ * HDIM;

    #pragma unroll
    for (int it = 0; it < 4; it++) {
        int id = tid + it * 256;
        int r = id >> 3, c = (id & 7) << 3;
        CP_ASYNC16(baseQ + (r * QP + c) * 2, qb + r * HDIM + c);
    }
    #pragma unroll
    for (int it = 0; it < 2; it++) {
        int id = tid + it * 256;
        int r = id >> 3, c = (id & 7) << 3;
        CP_ASYNC16(baseK + (r * QP + c) * 2, kb + r * HDIM + c);
        CP_ASYNC16(baseV + (r * QP + c) * 2, vb + r * HDIM + c);
    }
    CP_COMMIT();

    float m_run0 = -1e4f, m_run1 = -1e4f;
    float lacc[4] = {0.f, 0.f, 0.f, 0.f};
    float acc[8][4];
    #pragma unroll
    for (int j = 0; j < 8; j++)
        #pragma unroll
        for (int r = 0; r < 4; r++) acc[j][r] = 0.f;

    uint32_t qf[4][4];
    const float scale = 0.125f;
    const float L2E   = 1.44269504f;
    const uint32_t ONES = 0x3C003C00u;

    const int l15 = lane & 15, l7 = lane & 7;
    const int hi8 = (lane >> 4) << 3;
    const int b8  = ((lane >> 3) & 1) << 3;

    for (int kt = 0; kt < 8; kt++) {
        CP_WAIT(0);
        __syncthreads();
        if (kt + 1 < 8) {
            int bufn = ((kt + 1) & 1) * 64 * QP * 2;
            const __half* kn = kb + (size_t)(kt + 1) * 64 * HDIM;
            const __half* vn = vb + (size_t)(kt + 1) * 64 * HDIM;
            #pragma unroll
            for (int it = 0; it < 2; it++) {
                int id = tid + it * 256;
                int r = id >> 3, c = (id & 7) << 3;
                CP_ASYNC16(baseK + bufn + (r * QP + c) * 2, kn + r * HDIM + c);
                CP_ASYNC16(baseV + bufn + (r * QP + c) * 2, vn + r * HDIM + c);
            }
        }
        CP_COMMIT();

        if (kt == 0) {
            #pragma unroll
            for (int ks = 0; ks < 4; ks++) {
                uint32_t ad = baseQ + ((m0 + l15) * QP + ks * 16 + hi8) * 2;
                LDSM4(qf[ks][0], qf[ks][1], qf[ks][2], qf[ks][3], ad);
            }
        }

        const uint32_t kbuf = baseK + (kt & 1) * 64 * QP * 2;
        const uint32_t vbuf = baseV + (kt & 1) * 64 * QP * 2;

        float sc[8][4];
        #pragma unroll
        for (int j = 0; j < 8; j++)
            #pragma unroll
            for (int r = 0; r < 4; r++) sc[j][r] = 0.f;

        #pragma unroll
        for (int ks = 0; ks < 4; ks++) {
            #pragma unroll
            for (int g = 0; g < 4; g++) {
                uint32_t kd = kbuf + ((g * 16 + l7 + hi8) * QP + ks * 16 + b8) * 2;
                uint32_t k0r, k1r, k2r, k3r;
                LDSM4(k0r, k1r, k2r, k3r, kd);
                mma_f16(sc[2 * g],     qf[ks][0], qf[ks][1], qf[ks][2], qf[ks][3], k0r, k1r);
                mma_f16(sc[2 * g + 1], qf[ks][0], qf[ks][1], qf[ks][2], qf[ks][3], k2r, k3r);
            }
        }

        unsigned long long mlo = mask[((size_t)bb * SEQ + q0 + m0 + grp)     * 8 + kt];
        unsigned long long mhi = mask[((size_t)bb * SEQ + q0 + m0 + grp + 8) * 8 + kt];
        float mx0 = -1e30f, mx1 = -1e30f;
        #pragma unroll
        for (int j = 0; j < 8; j++) {
            int c0 = j * 8 + tid4 * 2;
            sc[j][0] = ((mlo >> c0) & 1)       ? sc[j][0] * scale : -1e30f;
            sc[j][1] = ((mlo >> (c0 + 1)) & 1) ? sc[j][1] * scale : -1e30f;
            sc[j][2] = ((mhi >> c0) & 1)       ? sc[j][2] * scale : -1e30f;
            sc[j][3] = ((mhi >> (c0 + 1)) & 1) ? sc[j][3] * scale : -1e30f;
            mx0 = fmaxf(mx0, fmaxf(sc[j][0], sc[j][1]));
            mx1 = fmaxf(mx1, fmaxf(sc[j][2], sc[j][3]));
        }
        mx0 = fmaxf(mx0, __shfl_xor_sync(0xffffffffu, mx0, 1));
        mx0 = fmaxf(mx0, __shfl_xor_sync(0xffffffffu, mx0, 2));
        mx1 = fmaxf(mx1, __shfl_xor_sync(0xffffffffu, mx1, 1));
        mx1 = fmaxf(mx1, __shfl_xor_sync(0xffffffffu, mx1, 2));

        float mn0 = fmaxf(m_run0, mx0), mn1 = fmaxf(m_run1, mx1);
        float f0 = __expf(m_run0 - mn0), f1 = __expf(m_run1 - mn1);
        m_run0 = mn0; m_run1 = mn1;

        uint32_t pl[8], ph[8];
        #pragma unroll
        for (int j = 0; j < 8; j++) {
            pl[j] = ex2_h2(pack_h2((sc[j][0] - mn0) * L2E, (sc[j][1] - mn0) * L2E));
            ph[j] = ex2_h2(pack_h2((sc[j][2] - mn1) * L2E, (sc[j][3] - mn1) * L2E));
        }

        #pragma unroll
        for (int j = 0; j < 8; j++) {
            acc[j][0] *= f0; acc[j][1] *= f0;
            acc[j][2] *= f1; acc[j][3] *= f1;
        }
        lacc[0] *= f0; lacc[1] *= f0;
        lacc[2] *= f1; lacc[3] *= f1;

        #pragma unroll
        for (int s = 0; s < 4; s++) {
            uint32_t a0 = pl[2 * s], a1 = ph[2 * s], a2 = pl[2 * s + 1], a3 = ph[2 * s + 1];
            mma_f16(lacc, a0, a1, a2, a3, ONES, ONES);
            #pragma unroll
            for (int g = 0; g < 4; g++) {
                uint32_t vd = vbuf + ((s * 16 + l15) * QP + g * 16 + hi8) * 2;
                uint32_t v0r, v1r, v2r, v3r;
                LDSM4T(v0r, v1r, v2r, v3r, vd);
                mma_f16(acc[2 * g],     a0, a1, a2, a3, v0r, v1r);
                mma_f16(acc[2 * g + 1], a0, a1, a2, a3, v2r, v3r);
            }
        }
    }

    const float inv0 = 1.0f / lacc[0];
    const float inv1 = 1.0f / lacc[2];
    const int rlo = q0 + m0 + grp, rhi = rlo + 8;
    #pragma unroll
    for (int j = 0; j < 8; j++) {
        int d = hh * HDIM + j * 8 + tid4 * 2;
        *(__half2*)(out + ((size_t)bb * SEQ + rlo) * DIM + d) =
            __floats2half2_rn(acc[j][0] * inv0, acc[j][1] * inv0);
        *(__half2*)(out + ((size_t)bb * SEQ + rhi) * DIM + d) =
            __floats2half2_rn(acc[j][2] * inv1, acc[j][3] * inv1);
    }
}

// ---------------------------------------------------------------------------
extern "C" void kernel_launch(void* const* d_in, const int* in_sizes, int n_in,
                              void* d_out, int out_size)
{
    const float* x   = (const float*)d_in[0];
    const int*   adj = (const int*)  d_in[1];
    const float* wq  = (const float*)d_in[2];
    const float* bq  = (const float*)d_in[3];
    const float* wk  = (const float*)d_in[4];
    const float* bk  = (const float*)d_in[5];
    const float* wv  = (const float*)d_in[6];
    const float* bv  = (const float*)d_in[7];
    const float* wo  = (const float*)d_in[8];
    const float* bo  = (const float*)d_in[9];
    const float* g1  = (const float*)d_in[10];
    const float* b1  = (const float*)d_in[11];
    const float* g2  = (const float*)d_in[12];
    const float* b2  = (const float*)d_in[13];
    const float* w1  = (const float*)d_in[14];
    const float* bf1 = (const float*)d_in[15];
    const float* w2  = (const float*)d_in[16];
    const float* bf2 = (const float*)d_in[17];
    float* out = (float*)d_out;

    __half *pln, *pq, *pk, *pv, *patt, *pgelu, *pw;
    float  *pout1, *pbqkv;
    unsigned long long* pmask;
    cudaGetSymbolAddress((void**)&pln,   h_ln);
    cudaGetSymbolAddress((void**)&pq,    h_q);
    cudaGetSymbolAddress((void**)&pk,    h_k);
    cudaGetSymbolAddress((void**)&pv,    h_v);
    cudaGetSymbolAddress((void**)&patt,  h_att);
    cudaGetSymbolAddress((void**)&pgelu, h_gelu);
    cudaGetSymbolAddress((void**)&pw,    h_w);
    cudaGetSymbolAddress((void**)&pout1, g_out1);
    cudaGetSymbolAddress((void**)&pbqkv, g_bqkv);
    cudaGetSymbolAddress((void**)&pmask, g_mask);

    __half* wqkvH = pw;
    __half* woH   = pw + 3 * WELEM;
    __half* w1H   = pw + 4 * WELEM;
    __half* w2H   = pw + 4 * WELEM + FELEM;

    static cudaStream_t sSide = nullptr;
    static cudaEvent_t evRoot = nullptr, evW = nullptr, evM = nullptr;
    static bool attr_set = false;
    if (!attr_set) {
        cudaFuncSetAttribute(attn_flash, cudaFuncAttributeMaxDynamicSharedMemorySize, ATT_SMEM);
        cudaFuncSetAttribute(hgemm<0>, cudaFuncAttributeMaxDynamicSharedMemorySize, GEMM_SMEM);
        cudaFuncSetAttribute(hgemm<1>, cudaFuncAttributeMaxDynamicSharedMemorySize, GEMM_SMEM);
        cudaFuncSetAttribute(hgemm<2>, cudaFuncAttributeMaxDynamicSharedMemorySize, GEMM_SMEM);
        cudaStreamCreateWithFlags(&sSide, cudaStreamNonBlocking);
        cudaEventCreateWithFlags(&evRoot, cudaEventDisableTiming);
        cudaEventCreateWithFlags(&evW,    cudaEventDisableTiming);
        cudaEventCreateWithFlags(&evM,    cudaEventDisableTiming);
        attr_set = true;
    }

    // Fork: prep on side stream, LN1 on main (fork-join capturable)
    cudaEventRecord(evRoot, 0);
    cudaStreamWaitEvent(sSide, evRoot, 0);
    prep_weights<<<PREPW_BLOCKS, 256, 0, sSide>>>(wq, wk, wv, wo, w1, w2, bq, bk, bv);
    cudaEventRecord(evW, sSide);
    prep_mask<<<MASK_BLOCKS, 256, 0, sSide>>>(adj);
    cudaEventRecord(evM, sSide);

    ln_kernel<<<MROWS, 192>>>(x, g1, b1, pln);

    cudaStreamWaitEvent(0, evW, 0);

    // Fused QKV projection (N=2304)
    dim3 gqkv(3 * DIM / 128, MROWS / 128);
    hgemm<0><<<gqkv, 128, GEMM_SMEM>>>(pln, wqkvH, pbqkv, nullptr,
                                       pq, pk, pv, 3 * DIM, DIM);

    cudaStreamWaitEvent(0, evM, 0);

    // Flash attention
    attn_flash<<<dim3(SEQ / 128, BATCH * HEADS), 256, ATT_SMEM>>>(pq, pk, pv, pmask, patt);

    // Output projection + bias + residual(x)
    dim3 g768(DIM / 128, MROWS / 128);
    hgemm<1><<<g768, 128, GEMM_SMEM>>>(patt, woH, bo, x, pout1, nullptr, nullptr, DIM, DIM);

    // LN2
    ln_kernel<<<MROWS, 192>>>(pout1, g2, b2, pln);

    // FFN1 + GELU
    dim3 g3072(DFF / 128, MROWS / 128);
    hgemm<2><<<g3072, 128, GEMM_SMEM>>>(pln, w1H, bf1, nullptr, pgelu, nullptr, nullptr, DFF, DIM);

    // FFN2 + bias + residual(out1) -> final output
    hgemm<1><<<g768, 128, GEMM_SMEM>>>(pgelu, w2H, bf2, pout1, out, nullptr, nullptr, DIM, DFF);
}

// round 17
// speedup vs baseline: 1.1040x; 1.0590x over previous
#include <cuda_runtime.h>
#include <cuda_fp16.h>
#include <math.h>
#include <stdint.h>

// Problem constants
static constexpr int BATCH = 32;
static constexpr int SEQ   = 512;
static constexpr int DIM   = 768;
static constexpr int HEADS = 12;
static constexpr int HDIM  = 64;
static constexpr int MROWS = BATCH * SEQ;   // 16384
static constexpr int DFF   = 3072;
static constexpr int HROWS = MROWS / 2;     // 8192 rows per half

// Scratch (device globals — allocation-free rule)
__device__ __half h_ln  [MROWS * DIM];
__device__ __half h_q   [MROWS * DIM];
__device__ __half h_k   [MROWS * DIM];
__device__ __half h_v   [MROWS * DIM];
__device__ __half h_att [MROWS * DIM];
__device__ __half h_gelu[MROWS * DFF];
__device__ float  g_out1[MROWS * DIM];
__device__ __half h_w   [4 * DIM * DIM + 2 * DIM * DFF];
__device__ float  g_bqkv[3 * DIM];
__device__ unsigned long long g_mask[BATCH * SEQ * 8];

// ---------------------------------------------------------------------------
// Helpers
// ---------------------------------------------------------------------------
__device__ __forceinline__ uint32_t smem_u32(const void* p) {
    uint32_t a;
    asm("{ .reg .u64 t; cvta.to.shared.u64 t, %1; cvt.u32.u64 %0, t; }" : "=r"(a) : "l"(p));
    return a;
}
__device__ __forceinline__ uint32_t pack_h2(float a, float b) {
    __half2 t = __floats2half2_rn(a, b);
    return *reinterpret_cast<uint32_t*>(&t);
}
__device__ __forceinline__ uint32_t ex2_h2(uint32_t t) {
    uint32_t r;
    asm("ex2.approx.f16x2 %0, %1;" : "=r"(r) : "r"(t));
    return r;
}
__device__ __forceinline__ void mma_f16(float* c, uint32_t a0, uint32_t a1,
                                        uint32_t a2, uint32_t a3,
                                        uint32_t b0, uint32_t b1) {
    asm volatile(
        "mma.sync.aligned.m16n8k16.row.col.f32.f16.f16.f32 "
        "{%0,%1,%2,%3}, {%4,%5,%6,%7}, {%8,%9}, {%0,%1,%2,%3};"
        : "+f"(c[0]), "+f"(c[1]), "+f"(c[2]), "+f"(c[3])
        : "r"(a0), "r"(a1), "r"(a2), "r"(a3), "r"(b0), "r"(b1));
}
#define LDSM4(r0, r1, r2, r3, addr)                                            \
    asm volatile("ldmatrix.sync.aligned.m8n8.x4.shared.b16 {%0,%1,%2,%3}, [%4];" \
        : "=r"(r0), "=r"(r1), "=r"(r2), "=r"(r3) : "r"(addr))
#define LDSM4T(r0, r1, r2, r3, addr)                                           \
    asm volatile("ldmatrix.sync.aligned.m8n8.x4.trans.shared.b16 {%0,%1,%2,%3}, [%4];" \
        : "=r"(r0), "=r"(r1), "=r"(r2), "=r"(r3) : "r"(addr))
#define CP_ASYNC16(dst, src) \
    asm volatile("cp.async.cg.shared.global [%0], [%1], 16;" :: "r"(dst), "l"(src))
#define CP_COMMIT()  asm volatile("cp.async.commit_group;" ::: "memory")
#define CP_WAIT(N)   asm volatile("cp.async.wait_group %0;" :: "n"(N) : "memory")

// ---------------------------------------------------------------------------
// Prep A: weights fp32->fp16. Wq/Wk/Wv packed FUSED: h_w[k*2304 + c].
// ---------------------------------------------------------------------------
static constexpr int WELEM = DIM * DIM;               // 589824
static constexpr int FELEM = DIM * DFF;               // 2359296
static constexpr int TOTW  = 4 * WELEM + 2 * FELEM;
static constexpr int PREPW_BLOCKS = TOTW / (256 * 8) + 2;

__global__ __launch_bounds__(256) void prep_weights(
    const float* __restrict__ wq, const float* __restrict__ wk,
    const float* __restrict__ wv, const float* __restrict__ wo,
    const float* __restrict__ w1, const float* __restrict__ w2,
    const float* __restrict__ bq, const float* __restrict__ bk,
    const float* __restrict__ bv)
{
    size_t E = ((size_t)blockIdx.x * 256 + threadIdx.x) * 8;
    if (E < (size_t)TOTW) {
        const float* src; size_t off;
        if (E < 3 * (size_t)WELEM) {
            size_t k = E / 2304, c = E - k * 2304;
            int sel = (int)(c / DIM);
            src = (sel == 0) ? wq : (sel == 1) ? wk : wv;
            off = k * DIM + (c - (size_t)sel * DIM);
        } else if (E < 4 * (size_t)WELEM) { src = wo; off = E - 3 * (size_t)WELEM; }
        else if (E < 4 * (size_t)WELEM + FELEM) { src = w1; off = E - 4 * (size_t)WELEM; }
        else { src = w2; off = E - 4 * (size_t)WELEM - FELEM; }
        float4 v0 = *(const float4*)(src + off);
        float4 v1 = *(const float4*)(src + off + 4);
        uint4 o;
        o.x = pack_h2(v0.x, v0.y); o.y = pack_h2(v0.z, v0.w);
        o.z = pack_h2(v1.x, v1.y); o.w = pack_h2(v1.z, v1.w);
        *(uint4*)(h_w + E) = o;
    } else {
        int i = (int)(((size_t)blockIdx.x * 256 + threadIdx.x) - TOTW / 8);
        if (i < 3 * DIM) {
            int sel = i / DIM, off = i - sel * DIM;
            const float* src = (sel == 0) ? bq : (sel == 1) ? bk : bv;
            g_bqkv[i] = src[off];
        }
    }
}

// Prep B: adjacency bitmask
static constexpr int MASK_BLOCKS = (BATCH * SEQ * 8) / 256;   // 512
__global__ __launch_bounds__(256) void prep_mask(const int* __restrict__ adj)
{
    int idx = blockIdx.x * 256 + threadIdx.x;
    const int* src = adj + (size_t)idx * 64;
    unsigned long long m = 0;
    #pragma unroll
    for (int i = 0; i < 16; i++) {
        int4 a = ((const int4*)src)[i];
        m |= ((unsigned long long)(a.x != 0)) << (4 * i + 0);
        m |= ((unsigned long long)(a.y != 0)) << (4 * i + 1);
        m |= ((unsigned long long)(a.z != 0)) << (4 * i + 2);
        m |= ((unsigned long long)(a.w != 0)) << (4 * i + 3);
    }
    g_mask[idx] = m;
}

// ---------------------------------------------------------------------------
// fp16 mma GEMM — R16 core: CTA 128x128, 4 warps (2x2), warp tile 64x64,
// 128 threads, 256 regs. 4-stage K32 cp.async, CP_WAIT(2), interleaved issue.
// rbase: row offset (batch-split dual-stream).
// EPI 0: +bias, permuted half store; Nc=2304 routes to Cq/Ck/Cv [B,H,N,64]
// EPI 1: +bias +res(fp32), fp32 store
// EPI 2: +bias, exact GELU, half store
// ---------------------------------------------------------------------------
static constexpr int GST  = 4;
static constexpr int A_ST = 128 * 40;
static constexpr int B_ST = 32 * 136;
static constexpr int GEMM_SMEM = GST * (A_ST + B_ST) * 2;   // 75776 B

template <int EPI>
__global__ __launch_bounds__(128, 2) void hgemm(
    const __half* __restrict__ A, const __half* __restrict__ W,
    const float* __restrict__ bias, const float* __restrict__ res,
    void* __restrict__ Cv, void* __restrict__ Cv2, void* __restrict__ Cv3,
    int Nc, int K, int rbase)
{
    extern __shared__ __half hsm[];
    const uint32_t baseA = smem_u32(hsm);
    const uint32_t baseB = smem_u32(hsm + GST * A_ST);

    const int tid  = threadIdx.x;
    const int wid  = tid >> 5, lane = tid & 31;
    const int grp  = lane >> 2, tid4 = lane & 3;
    const int wm   = (wid >> 1) * 64;
    const int wn   = (wid & 1) * 64;
    const int row0 = blockIdx.y * 128 + rbase;
    const int col0 = blockIdx.x * 128;

    float acc[4][8][4];
    #pragma unroll
    for (int t = 0; t < 4; t++)
        #pragma unroll
        for (int j = 0; j < 8; j++)
            #pragma unroll
            for (int r = 0; r < 4; r++) acc[t][j][r] = 0.f;

    const int nst = K >> 5;

    auto issue_half = [&](int s, int half) {
        const int b = s & 3;
        const int k0 = s << 5;
        #pragma unroll
        for (int it = half * 2; it < half * 2 + 2; it++) {
            int id = tid + it * 128;
            int ar = id >> 2, ac = (id & 3) << 3;
            CP_ASYNC16(baseA + (b * A_ST + ar * 40 + ac) * 2,
                       A + (size_t)(row0 + ar) * K + k0 + ac);
            int br = id >> 4, bc = (id & 15) << 3;
            CP_ASYNC16(baseB + (b * B_ST + br * 136 + bc) * 2,
                       W + (size_t)(k0 + br) * Nc + col0 + bc);
        }
    };
    auto issue = [&](int s) { issue_half(s, 0); issue_half(s, 1); };

    issue(0); CP_COMMIT();
    issue(1); CP_COMMIT();
    issue(2); CP_COMMIT();

    const int a_row = (lane & 15), a_k8 = (lane >> 4) << 3;
    const int b_k   = (lane & 15), b_n8 = (lane >> 4) << 3;

    for (int st = 0; st < nst; st++) {
        CP_WAIT(2);
        __syncthreads();

        const uint32_t ab = baseA + (st & 3) * A_ST * 2;
        const uint32_t bb = baseB + (st & 3) * B_ST * 2;
        const bool more = (st + 3 < nst);

        uint32_t af0[4][4], bf0[4][4];
        #pragma unroll
        for (int t = 0; t < 4; t++) {
            uint32_t ad = ab + ((wm + t * 16 + a_row) * 40 + a_k8) * 2;
            LDSM4(af0[t][0], af0[t][1], af0[t][2], af0[t][3], ad);
        }
        #pragma unroll
        for (int g = 0; g < 4; g++) {
            uint32_t bd = bb + (b_k * 136 + wn + g * 16 + b_n8) * 2;
            LDSM4T(bf0[g][0], bf0[g][1], bf0[g][2], bf0[g][3], bd);
        }
        if (more) issue_half(st + 3, 0);

        #pragma unroll
        for (int t = 0; t < 4; t++)
            #pragma unroll
            for (int j = 0; j < 8; j++)
                mma_f16(acc[t][j], af0[t][0], af0[t][1], af0[t][2], af0[t][3],
                        bf0[j >> 1][(j & 1) * 2], bf0[j >> 1][(j & 1) * 2 + 1]);

        if (more) issue_half(st + 3, 1);
        CP_COMMIT();

        uint32_t af1[4][4], bf1r[4][4];
        #pragma unroll
        for (int t = 0; t < 4; t++) {
            uint32_t ad = ab + ((wm + t * 16 + a_row) * 40 + 16 + a_k8) * 2;
            LDSM4(af1[t][0], af1[t][1], af1[t][2], af1[t][3], ad);
        }
        #pragma unroll
        for (int g = 0; g < 4; g++) {
            uint32_t bd = bb + ((16 + b_k) * 136 + wn + g * 16 + b_n8) * 2;
            LDSM4T(bf1r[g][0], bf1r[g][1], bf1r[g][2], bf1r[g][3], bd);
        }
        #pragma unroll
        for (int t = 0; t < 4; t++)
            #pragma unroll
            for (int j = 0; j < 8; j++)
                mma_f16(acc[t][j], af1[t][0], af1[t][1], af1[t][2], af1[t][3],
                        bf1r[j >> 1][(j & 1) * 2], bf1r[j >> 1][(j & 1) * 2 + 1]);
    }

    #pragma unroll
    for (int t = 0; t < 4; t++) {
        int r_lo = row0 + wm + t * 16 + grp;
        int r_hi = r_lo + 8;
        #pragma unroll
        for (int j = 0; j < 8; j++) {
            int c = col0 + wn + j * 8 + tid4 * 2;
            float b0 = bias[c], b1 = bias[c + 1];
            float v00 = acc[t][j][0] + b0, v01 = acc[t][j][1] + b1;
            float v10 = acc[t][j][2] + b0, v11 = acc[t][j][3] + b1;
            if (EPI == 0) {
                int sel = c / DIM;
                int cc  = c - sel * DIM;
                __half* C = (sel == 0) ? (__half*)Cv : (sel == 1) ? (__half*)Cv2
                                                                  : (__half*)Cv3;
                int h = cc >> 6, d = cc & 63;
                int blo = r_lo >> 9, nlo = r_lo & 511;
                int bhi = r_hi >> 9, nhi = r_hi & 511;
                *(__half2*)(C + (((size_t)(blo * HEADS + h)) * SEQ + nlo) * HDIM + d) =
                    __floats2half2_rn(v00, v01);
                *(__half2*)(C + (((size_t)(bhi * HEADS + h)) * SEQ + nhi) * HDIM + d) =
                    __floats2half2_rn(v10, v11);
            } else if (EPI == 1) {
                float* C = (float*)Cv;
                const float2 r0 = *(const float2*)(res + (size_t)r_lo * Nc + c);
                const float2 r1 = *(const float2*)(res + (size_t)r_hi * Nc + c);
                *(float2*)(C + (size_t)r_lo * Nc + c) = make_float2(v00 + r0.x, v01 + r0.y);
                *(float2*)(C + (size_t)r_hi * Nc + c) = make_float2(v10 + r1.x, v11 + r1.y);
            } else {
                __half* C = (__half*)Cv;
                const float is2 = 0.70710678118654752f;
                v00 = 0.5f * v00 * (1.0f + erff(v00 * is2));
                v01 = 0.5f * v01 * (1.0f + erff(v01 * is2));
                v10 = 0.5f * v10 * (1.0f + erff(v10 * is2));
                v11 = 0.5f * v11 * (1.0f + erff(v11 * is2));
                *(__half2*)(C + (size_t)r_lo * Nc + c) = __floats2half2_rn(v00, v01);
                *(__half2*)(C + (size_t)r_hi * Nc + c) = __floats2half2_rn(v10, v11);
            }
        }
    }
}

// ---------------------------------------------------------------------------
// LayerNorm: fp32 in -> half out. 192 threads, float4 path. rbase = row offset.
// ---------------------------------------------------------------------------
__global__ __launch_bounds__(192) void ln_kernel(
    const float* __restrict__ x, const float* __restrict__ g,
    const float* __restrict__ b, __half* __restrict__ y, int rbase)
{
    int row = blockIdx.x + rbase;
    int tid = threadIdx.x;
    float4 v = *(const float4*)(x + (size_t)row * DIM + tid * 4);
    float s  = v.x + v.y + v.z + v.w;
    float ss = v.x * v.x + v.y * v.y + v.z * v.z + v.w * v.w;
    #pragma unroll
    for (int o = 16; o > 0; o >>= 1) {
        s  += __shfl_xor_sync(0xffffffffu, s, o);
        ss += __shfl_xor_sync(0xffffffffu, ss, o);
    }
    __shared__ float sh_s[6], sh_ss[6];
    int w = tid >> 5, l = tid & 31;
    if (l == 0) { sh_s[w] = s; sh_ss[w] = ss; }
    __syncthreads();
    float ts = 0.f, tss = 0.f;
    #pragma unroll
    for (int i = 0; i < 6; i++) { ts += sh_s[i]; tss += sh_ss[i]; }
    float mean = ts * (1.0f / DIM);
    float var  = tss * (1.0f / DIM) - mean * mean;
    float inv  = rsqrtf(var + 1e-5f);
    float4 gg = *(const float4*)(g + tid * 4);
    float4 bb = *(const float4*)(b + tid * 4);
    __half2 o0 = __floats2half2_rn((v.x - mean) * inv * gg.x + bb.x,
                                   (v.y - mean) * inv * gg.y + bb.y);
    __half2 o1 = __floats2half2_rn((v.z - mean) * inv * gg.z + bb.z,
                                   (v.w - mean) * inv * gg.w + bb.w);
    __half2* yr = (__half2*)(y + (size_t)row * DIM + tid * 4);
    yr[0] = o0; yr[1] = o1;
}

// ---------------------------------------------------------------------------
// Flash attention (ex2.approx.f16x2 softmax, MMA l-sum). bhbase = b*h offset.
// ---------------------------------------------------------------------------
static constexpr int QP   = 72;
static constexpr int O_Q  = 0;
static constexpr int O_K  = 128 * QP;
static constexpr int O_V  = O_K + 2 * 64 * QP;
static constexpr int ATT_SMEM = (O_V + 2 * 64 * QP) * 2;   // 55296 B

__global__ __launch_bounds__(256, 2) void attn_flash(
    const __half* __restrict__ q, const __half* __restrict__ kin,
    const __half* __restrict__ v, const unsigned long long* __restrict__ mask,
    __half* __restrict__ out, int bhbase)
{
    extern __shared__ __half hsm[];
    const uint32_t baseQ = smem_u32(hsm + O_Q);
    const uint32_t baseK = smem_u32(hsm + O_K);
    const uint32_t baseV = smem_u32(hsm + O_V);

    const int tid  = threadIdx.x;
    const int wid  = tid >> 5, lane = tid & 31;
    const int grp  = lane >> 2, tid4 = lane & 3;
    const int m0   = wid * 16;
    const int bh   = blockIdx.y + bhbase;
    const int bb   = bh / HEADS, hh = bh % HEADS;
    const int q0   = blockIdx.x * 128;

    const __half* qb = q   + (size_t)bh * SEQ * HDIM + (size_t)q0 * HDIM;
    const __half* kb = kin + (size_t)bh * SEQ * HDIM;
    const __half* vb = v   + (size_t)bh * SEQ * HDIM;

    #pragma unroll
    for (int it = 0; it < 4; it++) {
        int id = tid + it * 256;
        int r = id >> 3, c = (id & 7) << 3;
        CP_ASYNC16(baseQ + (r * QP + c) * 2, qb + r * HDIM + c);
    }
    #pragma unroll
    for (int it = 0; it < 2; it++) {
        int id = tid + it * 256;
        int r = id >> 3, c = (id & 7) << 3;
        CP_ASYNC16(baseK + (r * QP + c) * 2, kb + r * HDIM + c);
        CP_ASYNC16(baseV + (r * QP + c) * 2, vb + r * HDIM + c);
    }
    CP_COMMIT();

    float m_run0 = -1e4f, m_run1 = -1e4f;
    float lacc[4] = {0.f, 0.f, 0.f, 0.f};
    float acc[8][4];
    #pragma unroll
    for (int j = 0; j < 8; j++)
        #pragma unroll
        for (int r = 0; r < 4; r++) acc[j][r] = 0.f;

    uint32_t qf[4][4];
    const float scale = 0.125f;
    const float L2E   = 1.44269504f;
    const uint32_t ONES = 0x3C003C00u;

    const int l15 = lane & 15, l7 = lane & 7;
    const int hi8 = (lane >> 4) << 3;
    const int b8  = ((lane >> 3) & 1) << 3;

    for (int kt = 0; kt < 8; kt++) {
        CP_WAIT(0);
        __syncthreads();
        if (kt + 1 < 8) {
            int bufn = ((kt + 1) & 1) * 64 * QP * 2;
            const __half* kn = kb + (size_t)(kt + 1) * 64 * HDIM;
            const __half* vn = vb + (size_t)(kt + 1) * 64 * HDIM;
            #pragma unroll
            for (int it = 0; it < 2; it++) {
                int id = tid + it * 256;
                int r = id >> 3, c = (id & 7) << 3;
                CP_ASYNC16(baseK + bufn + (r * QP + c) * 2, kn + r * HDIM + c);
                CP_ASYNC16(baseV + bufn + (r * QP + c) * 2, vn + r * HDIM + c);
            }
        }
        CP_COMMIT();

        if (kt == 0) {
            #pragma unroll
            for (int ks = 0; ks < 4; ks++) {
                uint32_t ad = baseQ + ((m0 + l15) * QP + ks * 16 + hi8) * 2;
                LDSM4(qf[ks][0], qf[ks][1], qf[ks][2], qf[ks][3], ad);
            }
        }

        const uint32_t kbuf = baseK + (kt & 1) * 64 * QP * 2;
        const uint32_t vbuf = baseV + (kt & 1) * 64 * QP * 2;

        float sc[8][4];
        #pragma unroll
        for (int j = 0; j < 8; j++)
            #pragma unroll
            for (int r = 0; r < 4; r++) sc[j][r] = 0.f;

        #pragma unroll
        for (int ks = 0; ks < 4; ks++) {
            #pragma unroll
            for (int g = 0; g < 4; g++) {
                uint32_t kd = kbuf + ((g * 16 + l7 + hi8) * QP + ks * 16 + b8) * 2;
                uint32_t k0r, k1r, k2r, k3r;
                LDSM4(k0r, k1r, k2r, k3r, kd);
                mma_f16(sc[2 * g],     qf[ks][0], qf[ks][1], qf[ks][2], qf[ks][3], k0r, k1r);
                mma_f16(sc[2 * g + 1], qf[ks][0], qf[ks][1], qf[ks][2], qf[ks][3], k2r, k3r);
            }
        }

        unsigned long long mlo = mask[((size_t)bb * SEQ + q0 + m0 + grp)     * 8 + kt];
        unsigned long long mhi = mask[((size_t)bb * SEQ + q0 + m0 + grp + 8) * 8 + kt];
        float mx0 = -1e30f, mx1 = -1e30f;
        #pragma unroll
        for (int j = 0; j < 8; j++) {
            int c0 = j * 8 + tid4 * 2;
            sc[j][0] = ((mlo >> c0) & 1)       ? sc[j][0] * scale : -1e30f;
            sc[j][1] = ((mlo >> (c0 + 1)) & 1) ? sc[j][1] * scale : -1e30f;
            sc[j][2] = ((mhi >> c0) & 1)       ? sc[j][2] * scale : -1e30f;
            sc[j][3] = ((mhi >> (c0 + 1)) & 1) ? sc[j][3] * scale : -1e30f;
            mx0 = fmaxf(mx0, fmaxf(sc[j][0], sc[j][1]));
            mx1 = fmaxf(mx1, fmaxf(sc[j][2], sc[j][3]));
        }
        mx0 = fmaxf(mx0, __shfl_xor_sync(0xffffffffu, mx0, 1));
        mx0 = fmaxf(mx0, __shfl_xor_sync(0xffffffffu, mx0, 2));
        mx1 = fmaxf(mx1, __shfl_xor_sync(0xffffffffu, mx1, 1));
        mx1 = fmaxf(mx1, __shfl_xor_sync(0xffffffffu, mx1, 2));

        float mn0 = fmaxf(m_run0, mx0), mn1 = fmaxf(m_run1, mx1);
        float f0 = __expf(m_run0 - mn0), f1 = __expf(m_run1 - mn1);
        m_run0 = mn0; m_run1 = mn1;

        uint32_t pl[8], ph[8];
        #pragma unroll
        for (int j = 0; j < 8; j++) {
            pl[j] = ex2_h2(pack_h2((sc[j][0] - mn0) * L2E, (sc[j][1] - mn0) * L2E));
            ph[j] = ex2_h2(pack_h2((sc[j][2] - mn1) * L2E, (sc[j][3] - mn1) * L2E));
        }

        #pragma unroll
        for (int j = 0; j < 8; j++) {
            acc[j][0] *= f0; acc[j][1] *= f0;
            acc[j][2] *= f1; acc[j][3] *= f1;
        }
        lacc[0] *= f0; lacc[1] *= f0;
        lacc[2] *= f1; lacc[3] *= f1;

        #pragma unroll
        for (int s = 0; s < 4; s++) {
            uint32_t a0 = pl[2 * s], a1 = ph[2 * s], a2 = pl[2 * s + 1], a3 = ph[2 * s + 1];
            mma_f16(lacc, a0, a1, a2, a3, ONES, ONES);
            #pragma unroll
            for (int g = 0; g < 4; g++) {
                uint32_t vd = vbuf + ((s * 16 + l15) * QP + g * 16 + hi8) * 2;
                uint32_t v0r, v1r, v2r, v3r;
                LDSM4T(v0r, v1r, v2r, v3r, vd);
                mma_f16(acc[2 * g],     a0, a1, a2, a3, v0r, v1r);
                mma_f16(acc[2 * g + 1], a0, a1, a2, a3, v2r, v3r);
            }
        }
    }

    const float inv0 = 1.0f / lacc[0];
    const float inv1 = 1.0f / lacc[2];
    const int rlo = q0 + m0 + grp, rhi = rlo + 8;
    #pragma unroll
    for (int j = 0; j < 8; j++) {
        int d = hh * HDIM + j * 8 + tid4 * 2;
        *(__half2*)(out + ((size_t)bb * SEQ + rlo) * DIM + d) =
            __floats2half2_rn(acc[j][0] * inv0, acc[j][1] * inv0);
        *(__half2*)(out + ((size_t)bb * SEQ + rhi) * DIM + d) =
            __floats2half2_rn(acc[j][2] * inv1, acc[j][3] * inv1);
    }
}

// ---------------------------------------------------------------------------
extern "C" void kernel_launch(void* const* d_in, const int* in_sizes, int n_in,
                              void* d_out, int out_size)
{
    const float* x   = (const float*)d_in[0];
    const int*   adj = (const int*)  d_in[1];
    const float* wq  = (const float*)d_in[2];
    const float* bq  = (const float*)d_in[3];
    const float* wk  = (const float*)d_in[4];
    const float* bk  = (const float*)d_in[5];
    const float* wv  = (const float*)d_in[6];
    const float* bv  = (const float*)d_in[7];
    const float* wo  = (const float*)d_in[8];
    const float* bo  = (const float*)d_in[9];
    const float* g1  = (const float*)d_in[10];
    const float* b1  = (const float*)d_in[11];
    const float* g2  = (const float*)d_in[12];
    const float* b2  = (const float*)d_in[13];
    const float* w1  = (const float*)d_in[14];
    const float* bf1 = (const float*)d_in[15];
    const float* w2  = (const float*)d_in[16];
    const float* bf2 = (const float*)d_in[17];
    float* out = (float*)d_out;

    __half *pln, *pq, *pk, *pv, *patt, *pgelu, *pw;
    float  *pout1, *pbqkv;
    unsigned long long* pmask;
    cudaGetSymbolAddress((void**)&pln,   h_ln);
    cudaGetSymbolAddress((void**)&pq,    h_q);
    cudaGetSymbolAddress((void**)&pk,    h_k);
    cudaGetSymbolAddress((void**)&pv,    h_v);
    cudaGetSymbolAddress((void**)&patt,  h_att);
    cudaGetSymbolAddress((void**)&pgelu, h_gelu);
    cudaGetSymbolAddress((void**)&pw,    h_w);
    cudaGetSymbolAddress((void**)&pout1, g_out1);
    cudaGetSymbolAddress((void**)&pbqkv, g_bqkv);
    cudaGetSymbolAddress((void**)&pmask, g_mask);

    __half* wqkvH = pw;
    __half* woH   = pw + 3 * WELEM;
    __half* w1H   = pw + 4 * WELEM;
    __half* w2H   = pw + 4 * WELEM + FELEM;

    static cudaStream_t sB = nullptr, sP = nullptr;
    static cudaEvent_t evRoot = nullptr, evW = nullptr, evM = nullptr, evB = nullptr;
    static bool attr_set = false;
    if (!attr_set) {
        cudaFuncSetAttribute(attn_flash, cudaFuncAttributeMaxDynamicSharedMemorySize, ATT_SMEM);
        cudaFuncSetAttribute(hgemm<0>, cudaFuncAttributeMaxDynamicSharedMemorySize, GEMM_SMEM);
        cudaFuncSetAttribute(hgemm<1>, cudaFuncAttributeMaxDynamicSharedMemorySize, GEMM_SMEM);
        cudaFuncSetAttribute(hgemm<2>, cudaFuncAttributeMaxDynamicSharedMemorySize, GEMM_SMEM);
        cudaStreamCreateWithFlags(&sB, cudaStreamNonBlocking);
        cudaStreamCreateWithFlags(&sP, cudaStreamNonBlocking);
        cudaEventCreateWithFlags(&evRoot, cudaEventDisableTiming);
        cudaEventCreateWithFlags(&evW,    cudaEventDisableTiming);
        cudaEventCreateWithFlags(&evM,    cudaEventDisableTiming);
        cudaEventCreateWithFlags(&evB,    cudaEventDisableTiming);
        attr_set = true;
    }

    // Fork: prep on sP, half-1 chain on sB, half-0 chain on default.
    cudaEventRecord(evRoot, 0);
    cudaStreamWaitEvent(sP, evRoot, 0);
    cudaStreamWaitEvent(sB, evRoot, 0);
    prep_weights<<<PREPW_BLOCKS, 256, 0, sP>>>(wq, wk, wv, wo, w1, w2, bq, bk, bv);
    cudaEventRecord(evW, sP);
    prep_mask<<<MASK_BLOCKS, 256, 0, sP>>>(adj);
    cudaEventRecord(evM, sP);

    const int HB = HROWS;          // 8192 row offset for half 1
    const int BHB = (BATCH / 2) * HEADS;  // 192 bh offset for half 1
    dim3 gqkv(3 * DIM / 128, HROWS / 128);      // 18 x 64
    dim3 g768(DIM / 128, HROWS / 128);          // 6 x 64
    dim3 g3072(DFF / 128, HROWS / 128);         // 24 x 64
    dim3 gattn(SEQ / 128, BHB);                 // 4 x 192

    // LN1 (both halves)
    ln_kernel<<<HROWS, 192>>>(x, g1, b1, pln, 0);
    ln_kernel<<<HROWS, 192, 0, sB>>>(x, g1, b1, pln, HB);

    // QKV (needs weights)
    cudaStreamWaitEvent(0,  evW, 0);
    cudaStreamWaitEvent(sB, evW, 0);
    hgemm<0><<<gqkv, 128, GEMM_SMEM>>>(pln, wqkvH, pbqkv, nullptr,
                                       pq, pk, pv, 3 * DIM, DIM, 0);
    hgemm<0><<<gqkv, 128, GEMM_SMEM, sB>>>(pln, wqkvH, pbqkv, nullptr,
                                           pq, pk, pv, 3 * DIM, DIM, HB);

    // Attention (needs mask)
    cudaStreamWaitEvent(0,  evM, 0);
    cudaStreamWaitEvent(sB, evM, 0);
    attn_flash<<<gattn, 256, ATT_SMEM>>>(pq, pk, pv, pmask, patt, 0);
    attn_flash<<<gattn, 256, ATT_SMEM, sB>>>(pq, pk, pv, pmask, patt, BHB);

    // Output projection + residual(x)
    hgemm<1><<<g768, 128, GEMM_SMEM>>>(patt, woH, bo, x, pout1, nullptr, nullptr,
                                       DIM, DIM, 0);
    hgemm<1><<<g768, 128, GEMM_SMEM, sB>>>(patt, woH, bo, x, pout1, nullptr, nullptr,
                                           DIM, DIM, HB);

    // LN2
    ln_kernel<<<HROWS, 192>>>(pout1, g2, b2, pln, 0);
    ln_kernel<<<HROWS, 192, 0, sB>>>(pout1, g2, b2, pln, HB);

    // FFN1 + GELU
    hgemm<2><<<g3072, 128, GEMM_SMEM>>>(pln, w1H, bf1, nullptr, pgelu, nullptr, nullptr,
                                        DFF, DIM, 0);
    hgemm<2><<<g3072, 128, GEMM_SMEM, sB>>>(pln, w1H, bf1, nullptr, pgelu, nullptr, nullptr,
                                            DFF, DIM, HB);

    // FFN2 + residual(out1) -> final output
    hgemm<1><<<g768, 128, GEMM_SMEM>>>(pgelu, w2H, bf2, pout1, out, nullptr, nullptr,
                                       DIM, DFF, 0);
    hgemm<1><<<g768, 128, GEMM_SMEM, sB>>>(pgelu, w2H, bf2, pout1, out, nullptr, nullptr,
                                           DIM, DFF, HB);

    // Join half-1 back into the origin stream
    cudaEventRecord(evB, sB);
    cudaStreamWaitEvent(0, evB, 0);
}